// round 14
// baseline (speedup 1.0000x reference)
#include <cuda_runtime.h>
#include <cstdint>

#define NUM_EXPERTS 8
#define HIDDEN 2048
#define EXPERT_DIM 4096
#define TOKENS 1024

// fp16x2-packed operands as uint32 device globals (round-9-proven pattern).
// CRITICAL: these are referenced ONLY in device code (host-side references to
// __device__ symbols are invalid — root cause of rounds 6-8 failures).
__device__ uint32_t Xh32[(size_t)NUM_EXPERTS * TOKENS * (HIDDEN / 2)];          // 32MB  [e*t][H/2]
__device__ uint32_t W1h[(size_t)NUM_EXPERTS * 2 * EXPERT_DIM * (HIDDEN / 2)];   // 256MB [e][n 8192][H/2]
__device__ uint32_t W2h[(size_t)NUM_EXPERTS * HIDDEN * (EXPERT_DIM / 2)];       // 128MB [e][n 2048][I/2]
__device__ uint32_t Gh32[(size_t)NUM_EXPERTS * TOKENS * (EXPERT_DIM / 2)];      // 64MB  [e][t][I/2]

__device__ __forceinline__ uint32_t pack_h2(float a, float b) {
    uint32_t r;
    asm("cvt.rn.f16x2.f32 %0, %1, %2;" : "=r"(r) : "f"(b), "f"(a));
    return r;
}

__device__ __forceinline__ void mma_f16(float* c, const uint32_t* a, const uint32_t* b) {
    asm volatile(
        "mma.sync.aligned.m16n8k16.row.col.f32.f16.f16.f32 "
        "{%0,%1,%2,%3}, {%4,%5,%6,%7}, {%8,%9}, {%0,%1,%2,%3};\n"
        : "+f"(c[0]), "+f"(c[1]), "+f"(c[2]), "+f"(c[3])
        : "r"(a[0]), "r"(a[1]), "r"(a[2]), "r"(a[3]), "r"(b[0]), "r"(b[1]));
}

// Rows of 16 k-pair words (BK=32) padded to 20. 20g mod 32 distinct and ≡0 mod 4
// -> fragment loads across (g, tg) cover 32 banks (proven rounds 4-13).
#define R_ST 20

// ---------------------------------------------------------------------------
// Convert kernels. Destinations are device globals named IN DEVICE CODE.
// ---------------------------------------------------------------------------
__global__ __launch_bounds__(256) void convert_x_kernel(const float* __restrict__ X) {
    const size_t i4 = ((size_t)blockIdx.x * 256 + threadIdx.x) * 4;  // float index
    float4 v = *(const float4*)(X + i4);
    *(uint2*)(Xh32 + i4 / 2) = make_uint2(pack_h2(v.x, v.y), pack_h2(v.z, v.w));
}

// src [e][K][N] fp32 (n contiguous) -> global dst [e][N][K/2] fp16x2-words.
// which = 0 -> W1h (K=2048, N=8192);  which = 1 -> W2h (K=4096, N=2048).
__global__ __launch_bounds__(256) void transpose_w_kernel(
    const float* __restrict__ src, int K, int N, int which) {
    __shared__ float tile[32][33];
    const int e = blockIdx.z;
    const int n0 = blockIdx.x * 32, k0 = blockIdx.y * 32;
    const int tx = threadIdx.x & 31, ty = threadIdx.x >> 5;   // 32 x 8
    const float* s = src + (size_t)e * K * N;
    #pragma unroll
    for (int j = 0; j < 32; j += 8)
        tile[ty + j][tx] = s[(size_t)(k0 + ty + j) * N + n0 + tx];
    __syncthreads();
    uint32_t* d = (which ? W2h : W1h) + (size_t)e * N * (K / 2);
    const int w = threadIdx.x & 15;        // k-pair word within the 32-k tile
    const int r = threadIdx.x >> 4;        // 0..15 (+16)
    #pragma unroll
    for (int j = 0; j < 32; j += 16) {
        const int rr = r + j;
        d[(size_t)(n0 + rr) * (K / 2) + k0 / 2 + w] =
            pack_h2(tile[2 * w][rr], tile[2 * w + 1][rr]);
    }
}

// ---------------------------------------------------------------------------
// GEMM1 + silu. Block: 128 tokens x 64 gated cols. K=2048, BK=32 (nT=64).
// 8 warps = 4(M) x 2(N). Warp tile 32x32 dual. 2 CTAs/SM.
// All operands pre-packed fp16x2: staging = pure uint4 copies, no XOR swizzle.
// B smem rows: 0..63 = gate (W1h row n0+r), 64..127 = up (W1h row 4096+n0+r).
// ---------------------------------------------------------------------------
__global__ __launch_bounds__(256, 2) void gemm1_kernel() {
    __shared__ uint32_t As[2][128][R_ST];
    __shared__ uint32_t Bs[2][128][R_ST];

    const int e  = blockIdx.z;
    const int m0 = blockIdx.y * 128;
    const int n0 = blockIdx.x * 64;

    const int tid  = threadIdx.x;
    const int warp = tid >> 5;
    const int lane = tid & 31;
    const int wm = (warp >> 1) * 32;   // 4 warps in M
    const int wn = (warp & 1) * 32;    // 2 warps in N
    const int g  = lane >> 2;
    const int tg = lane & 3;

    const int LDA = HIDDEN / 2;   // 1024 words per row
    const uint32_t* Ap = Xh32 + (size_t)(e * TOKENS + m0) * LDA;
    const uint32_t* Bp = W1h + (size_t)e * (2 * EXPERT_DIM) * LDA;

    // staging: row pair (s_row, s_row+64), 16B chunk s_q
    const int s_row = tid >> 2;        // 0..63
    const int s_q   = tid & 3;
    const int bn0 = n0 + s_row;                 // gate row -> smem row s_row
    const int bn1 = 4096 + n0 + s_row;          // up row   -> smem row s_row+64

    uint4 ra[2], rb[2];

    // prologue: stage tile 0
    {
        ra[0] = *(const uint4*)(Ap + (size_t)s_row * LDA + s_q * 4);
        ra[1] = *(const uint4*)(Ap + (size_t)(s_row + 64) * LDA + s_q * 4);
        rb[0] = *(const uint4*)(Bp + (size_t)bn0 * LDA + s_q * 4);
        rb[1] = *(const uint4*)(Bp + (size_t)bn1 * LDA + s_q * 4);
        *(uint4*)&As[0][s_row][s_q * 4] = ra[0];
        *(uint4*)&As[0][s_row + 64][s_q * 4] = ra[1];
        *(uint4*)&Bs[0][s_row][s_q * 4] = rb[0];
        *(uint4*)&Bs[0][s_row + 64][s_q * 4] = rb[1];
    }
    __syncthreads();

    float accg[2][4][4] = {};
    float accu[2][4][4] = {};

    const int nT = HIDDEN / 32;  // 64
    #pragma unroll 1
    for (int kt = 0; kt < nT; ++kt) {
        const int buf = kt & 1;
        if (kt + 1 < nT) {
            const int kw = (kt + 1) * 16 + s_q * 4;
            ra[0] = *(const uint4*)(Ap + (size_t)s_row * LDA + kw);
            ra[1] = *(const uint4*)(Ap + (size_t)(s_row + 64) * LDA + kw);
            rb[0] = *(const uint4*)(Bp + (size_t)bn0 * LDA + kw);
            rb[1] = *(const uint4*)(Bp + (size_t)bn1 * LDA + kw);
        }

        #pragma unroll
        for (int ks = 0; ks < 2; ++ks) {
            const int k8 = ks * 8;
            uint32_t af[2][4];
            #pragma unroll
            for (int im = 0; im < 2; ++im) {
                const int r = wm + im * 16 + g;
                af[im][0] = As[buf][r][k8 + tg];
                af[im][1] = As[buf][r + 8][k8 + tg];
                af[im][2] = As[buf][r][k8 + tg + 4];
                af[im][3] = As[buf][r + 8][k8 + tg + 4];
            }
            uint32_t bg[4][2], bu[4][2];
            #pragma unroll
            for (int in = 0; in < 4; ++in) {
                const int cg = wn + in * 8 + g;
                bg[in][0] = Bs[buf][cg][k8 + tg];
                bg[in][1] = Bs[buf][cg][k8 + tg + 4];
                bu[in][0] = Bs[buf][cg + 64][k8 + tg];
                bu[in][1] = Bs[buf][cg + 64][k8 + tg + 4];
            }
            #pragma unroll
            for (int im = 0; im < 2; ++im) {
                #pragma unroll
                for (int in = 0; in < 4; ++in) {
                    mma_f16(accg[im][in], af[im], bg[in]);
                    mma_f16(accu[im][in], af[im], bu[in]);
                }
            }
        }

        if (kt + 1 < nT) {
            const int nb = (kt + 1) & 1;
            *(uint4*)&As[nb][s_row][s_q * 4] = ra[0];
            *(uint4*)&As[nb][s_row + 64][s_q * 4] = ra[1];
            *(uint4*)&Bs[nb][s_row][s_q * 4] = rb[0];
            *(uint4*)&Bs[nb][s_row + 64][s_q * 4] = rb[1];
        }
        __syncthreads();
    }

    // Epilogue: gated = up * silu(gate) -> Gh32 (fp16x2)
    uint32_t* Gp = Gh32 + (size_t)e * TOKENS * (EXPERT_DIM / 2);
    #pragma unroll
    for (int im = 0; im < 2; ++im) {
        #pragma unroll
        for (int in = 0; in < 4; ++in) {
            #pragma unroll
            for (int h = 0; h < 2; ++h) {
                const int r = m0 + wm + im * 16 + g + h * 8;
                const int c = n0 + wn + in * 8 + 2 * tg;
                const float gv0 = accg[im][in][h * 2 + 0];
                const float gv1 = accg[im][in][h * 2 + 1];
                const float uv0 = accu[im][in][h * 2 + 0];
                const float uv1 = accu[im][in][h * 2 + 1];
                const float s0 = gv0 / (1.0f + __expf(-gv0));
                const float s1 = gv1 / (1.0f + __expf(-gv1));
                Gp[(size_t)r * (EXPERT_DIM / 2) + (c >> 1)] = pack_h2(uv0 * s0, uv1 * s1);
            }
        }
    }
}

// ---------------------------------------------------------------------------
// GEMM2: Out[e] = G[e] (1024x4096 fp16) @ W2h[e] (fp16, n-major).
// Block 128x128, BK=32 (nT=128). 8 warps = 2(M) x 4(N). Warp tile 64x32.
// 2 CTAs/SM. Staging = pure uint4 copies.
// ---------------------------------------------------------------------------
__global__ __launch_bounds__(256, 2) void gemm2_kernel(float* __restrict__ Out) {
    __shared__ uint32_t As[2][128][R_ST];
    __shared__ uint32_t Bs[2][128][R_ST];

    const int e  = blockIdx.z;
    const int m0 = blockIdx.y * 128;
    const int n0 = blockIdx.x * 128;

    const int tid  = threadIdx.x;
    const int warp = tid >> 5;
    const int lane = tid & 31;
    const int wm = (warp >> 2) * 64;   // 2 warps in M
    const int wn = (warp & 3) * 32;    // 4 warps in N
    const int g  = lane >> 2;
    const int tg = lane & 3;

    const int LDA = EXPERT_DIM / 2;    // 2048 words per row
    const uint32_t* Ap = Gh32 + (size_t)(e * TOKENS + m0) * LDA;
    const uint32_t* Bp = W2h + (size_t)e * HIDDEN * LDA + (size_t)n0 * LDA;

    const int s_row = tid >> 2;
    const int s_q   = tid & 3;

    uint4 ra[2], rb[2];

    {
        ra[0] = *(const uint4*)(Ap + (size_t)s_row * LDA + s_q * 4);
        ra[1] = *(const uint4*)(Ap + (size_t)(s_row + 64) * LDA + s_q * 4);
        rb[0] = *(const uint4*)(Bp + (size_t)s_row * LDA + s_q * 4);
        rb[1] = *(const uint4*)(Bp + (size_t)(s_row + 64) * LDA + s_q * 4);
        *(uint4*)&As[0][s_row][s_q * 4] = ra[0];
        *(uint4*)&As[0][s_row + 64][s_q * 4] = ra[1];
        *(uint4*)&Bs[0][s_row][s_q * 4] = rb[0];
        *(uint4*)&Bs[0][s_row + 64][s_q * 4] = rb[1];
    }
    __syncthreads();

    float acc[4][4][4] = {};

    const int nT = EXPERT_DIM / 32;  // 128
    #pragma unroll 1
    for (int kt = 0; kt < nT; ++kt) {
        const int buf = kt & 1;
        if (kt + 1 < nT) {
            const int kw = (kt + 1) * 16 + s_q * 4;
            ra[0] = *(const uint4*)(Ap + (size_t)s_row * LDA + kw);
            ra[1] = *(const uint4*)(Ap + (size_t)(s_row + 64) * LDA + kw);
            rb[0] = *(const uint4*)(Bp + (size_t)s_row * LDA + kw);
            rb[1] = *(const uint4*)(Bp + (size_t)(s_row + 64) * LDA + kw);
        }

        #pragma unroll
        for (int ks = 0; ks < 2; ++ks) {
            const int k8 = ks * 8;
            uint32_t af[4][4];
            #pragma unroll
            for (int im = 0; im < 4; ++im) {
                const int r = wm + im * 16 + g;
                af[im][0] = As[buf][r][k8 + tg];
                af[im][1] = As[buf][r + 8][k8 + tg];
                af[im][2] = As[buf][r][k8 + tg + 4];
                af[im][3] = As[buf][r + 8][k8 + tg + 4];
            }
            uint32_t bf[4][2];
            #pragma unroll
            for (int in = 0; in < 4; ++in) {
                const int c = wn + in * 8 + g;
                bf[in][0] = Bs[buf][c][k8 + tg];
                bf[in][1] = Bs[buf][c][k8 + tg + 4];
            }
            #pragma unroll
            for (int im = 0; im < 4; ++im) {
                #pragma unroll
                for (int in = 0; in < 4; ++in) {
                    mma_f16(acc[im][in], af[im], bf[in]);
                }
            }
        }

        if (kt + 1 < nT) {
            const int nb = (kt + 1) & 1;
            *(uint4*)&As[nb][s_row][s_q * 4] = ra[0];
            *(uint4*)&As[nb][s_row + 64][s_q * 4] = ra[1];
            *(uint4*)&Bs[nb][s_row][s_q * 4] = rb[0];
            *(uint4*)&Bs[nb][s_row + 64][s_q * 4] = rb[1];
        }
        __syncthreads();
    }

    float* Optr = Out + (size_t)(e * TOKENS + m0) * HIDDEN + n0;
    #pragma unroll
    for (int im = 0; im < 4; ++im) {
        #pragma unroll
        for (int in = 0; in < 4; ++in) {
            #pragma unroll
            for (int h = 0; h < 2; ++h) {
                const int r = wm + im * 16 + g + h * 8;
                const int c = wn + in * 8 + 2 * tg;
                *(float2*)(Optr + (size_t)r * HIDDEN + c) =
                    make_float2(acc[im][in][h * 2 + 0], acc[im][in][h * 2 + 1]);
            }
        }
    }
}

extern "C" void kernel_launch(void* const* d_in, const int* in_sizes, int n_in,
                              void* d_out, int out_size) {
    const float* X  = (const float*)d_in[0];   // hidden_states [8192, 2048]
    const float* W1 = (const float*)d_in[1];   // gate_up_proj  [8, 2048, 8192]
    const float* W2 = (const float*)d_in[2];   // down_proj     [8, 4096, 2048]
    float* Out = (float*)d_out;                // [8192, 2048]

    // Converts (destination globals selected in device code, never host-passed)
    convert_x_kernel<<<(NUM_EXPERTS * TOKENS * HIDDEN) / (256 * 4), 256>>>(X);
    transpose_w_kernel<<<dim3(2 * EXPERT_DIM / 32, HIDDEN / 32, NUM_EXPERTS), 256>>>(
        W1, HIDDEN, 2 * EXPERT_DIM, 0);
    transpose_w_kernel<<<dim3(HIDDEN / 32, EXPERT_DIM / 32, NUM_EXPERTS), 256>>>(
        W2, EXPERT_DIM, HIDDEN, 1);

    dim3 blk(256);
    dim3 g1(EXPERT_DIM / 64, TOKENS / 128, NUM_EXPERTS);   // 64 x 8 x 8
    dim3 g2(HIDDEN / 128, TOKENS / 128, NUM_EXPERTS);      // 16 x 8 x 8
    gemm1_kernel<<<g1, blk>>>();
    gemm2_kernel<<<g2, blk>>>(Out);
}